// round 3
// baseline (speedup 1.0000x reference)
#include <cuda_runtime.h>

#define NN 50000
#define NE 800000
#define FIN 500
#define HD 96

// ---------------- device scratch (no allocations allowed) ----------------
__device__ int   g_cnt_out[NN];
__device__ int   g_cnt_in[NN];
__device__ float g_norm_out[NN];
__device__ float g_norm_in[NN];
__device__ int   g_coff[NN + 1];
__device__ int   g_cursor[NN];
__device__ int   g_csr_src[NE];
__device__ int   g_bsums[64];
__device__ float g_bufA[2 * NN * HD];   // GEMM outputs
__device__ float g_bufB[2 * NN * HD];   // SpMM outputs (layer-1 activations)
__device__ float g_wv[HD];
__device__ float g_bmsum;

// ---------------- packed f32x2 helpers (sm_103a) ----------------
typedef unsigned long long u64;

__device__ __forceinline__ u64 pk2(float v) {
    u64 r;
    asm("mov.b64 %0, {%1, %1};" : "=l"(r) : "r"(__float_as_uint(v)));
    return r;
}
__device__ __forceinline__ u64 fma2(u64 a, u64 b, u64 c) {
    u64 d;
    asm("fma.rn.f32x2 %0, %1, %2, %3;" : "=l"(d) : "l"(a), "l"(b), "l"(c));
    return d;
}
__device__ __forceinline__ void upk(u64 v, float& lo, float& hi) {
    unsigned int l, h;
    asm("mov.b64 {%0, %1}, %2;" : "=r"(l), "=r"(h) : "l"(v));
    lo = __uint_as_float(l);
    hi = __uint_as_float(h);
}

// ---------------- degrees / norms ----------------
__global__ void k_zero() {
    int i = blockIdx.x * blockDim.x + threadIdx.x;
    if (i < NN) { g_cnt_out[i] = 0; g_cnt_in[i] = 0; }
}

__global__ void k_deg(const int* __restrict__ src, const int* __restrict__ dst) {
    int e = blockIdx.x * blockDim.x + threadIdx.x;
    if (e < NE) {
        atomicAdd(&g_cnt_out[src[e]], 1);
        atomicAdd(&g_cnt_in[dst[e]], 1);
    }
}

__global__ void k_norm() {
    int i = blockIdx.x * blockDim.x + threadIdx.x;
    if (i < NN) {
        g_norm_out[i] = rsqrtf((float)max(g_cnt_out[i], 1));
        g_norm_in[i]  = rsqrtf((float)max(g_cnt_in[i], 1));
    }
}

// ---------------- CSR build: exclusive scan of in-degrees ----------------
__global__ void k_scan_part() {
    __shared__ int s[1024];
    int t = threadIdx.x;
    int i = blockIdx.x * 1024 + t;
    int c = (i < NN) ? g_cnt_in[i] : 0;
    s[t] = c;
    __syncthreads();
    for (int off = 1; off < 1024; off <<= 1) {
        int v = (t >= off) ? s[t - off] : 0;
        __syncthreads();
        s[t] += v;
        __syncthreads();
    }
    if (i < NN) g_coff[i] = s[t] - c;
    if (t == 1023) g_bsums[blockIdx.x] = s[t];
}

__global__ void k_scan_top(int nb) {
    if (threadIdx.x == 0) {
        int run = 0;
        for (int b = 0; b < nb; b++) { int v = g_bsums[b]; g_bsums[b] = run; run += v; }
    }
}

__global__ void k_scan_add() {
    int i = blockIdx.x * 1024 + threadIdx.x;
    if (i < NN) {
        int v = g_coff[i] + g_bsums[blockIdx.x];
        g_coff[i] = v;
        g_cursor[i] = v;
    }
    if (i == 0) g_coff[NN] = NE;
}

__global__ void k_scatter(const int* __restrict__ src, const int* __restrict__ dst) {
    int e = blockIdx.x * blockDim.x + threadIdx.x;
    if (e < NE) {
        int d = dst[e];
        int p = atomicAdd(&g_cursor[d], 1);
        g_csr_src[p] = src[e];
    }
}

// ---------------- Wm row-sums + bm sum (final GEMM collapsed) ----------------
__global__ void k_wv(const float* __restrict__ Wm, const float* __restrict__ bm) {
    int t = threadIdx.x;
    if (t < HD) {
        float s = 0.f;
        for (int j = 0; j < HD; j++) s += Wm[t * HD + j];
        g_wv[t] = s;
        if (t == 0) {
            float bs = 0.f;
            for (int j = 0; j < HD; j++) bs += bm[j];
            g_bmsum = bs;
        }
    }
}

// ---------------- tiled fp32 GEMM with packed f32x2 FMA ----------------
// C(g_bufA) = A @ W  [* norm_out in epilogue if SCALE]
// BM=128, BN=96, 256 threads; per thread 8 rows x 6 cols as 4 row-pairs x 6.
template <int K, int BK, bool SCALE>
__global__ __launch_bounds__(256, 3)
void k_gemm(const float* __restrict__ Ain, const float* __restrict__ W, int M) {
    __shared__ float As[BK][132];   // [k][row], padded stride
    __shared__ float Bs[BK][HD];

    const float* __restrict__ A = SCALE ? (const float*)g_bufB : Ain;
    const int tid = threadIdx.x;
    const int tx = tid & 15;        // 16 col-groups of 6
    const int ty = tid >> 4;        // 16 row-groups of 8
    const int m0 = blockIdx.x * 128;

    u64 accp[4][6];
#pragma unroll
    for (int i = 0; i < 4; i++)
#pragma unroll
        for (int j = 0; j < 6; j++) accp[i][j] = 0ull;

    for (int k0 = 0; k0 < K; k0 += BK) {
        // load A tile (128 rows x BK k) into As[k][row]
#pragma unroll
        for (int j = tid; j < 128 * BK; j += 256) {
            int r = j / BK;
            int k = j - r * BK;
            int m = m0 + r;
            As[k][r] = (m < M) ? A[m * K + k0 + k] : 0.f;
        }
        // load W tile (BK x 96)
        for (int j = tid; j < BK * HD; j += 256) {
            int k = j / HD;
            int n = j - k * HD;
            Bs[k][n] = W[(k0 + k) * HD + n];
        }
        __syncthreads();

#pragma unroll
        for (int k = 0; k < BK; k++) {
            const u64* ap = (const u64*)&As[k][ty * 8];
            u64 a01 = ap[0], a23 = ap[1], a45 = ap[2], a67 = ap[3];
            float2 q0 = *(const float2*)&Bs[k][tx * 6];
            float2 q1 = *(const float2*)&Bs[k][tx * 6 + 2];
            float2 q2 = *(const float2*)&Bs[k][tx * 6 + 4];
            float b[6] = {q0.x, q0.y, q1.x, q1.y, q2.x, q2.y};
#pragma unroll
            for (int j = 0; j < 6; j++) {
                u64 bb = pk2(b[j]);
                accp[0][j] = fma2(a01, bb, accp[0][j]);
                accp[1][j] = fma2(a23, bb, accp[1][j]);
                accp[2][j] = fma2(a45, bb, accp[2][j]);
                accp[3][j] = fma2(a67, bb, accp[3][j]);
            }
        }
        __syncthreads();
    }

#pragma unroll
    for (int i = 0; i < 4; i++) {
        int mlo = m0 + ty * 8 + 2 * i;
        float lo[6], hi[6];
#pragma unroll
        for (int j = 0; j < 6; j++) upk(accp[i][j], lo[j], hi[j]);
        if (mlo < M) {
            float s = 1.f;
            if (SCALE) s = g_norm_out[(mlo < NN) ? mlo : mlo - NN];
            float* c = g_bufA + mlo * HD + tx * 6;
#pragma unroll
            for (int j = 0; j < 6; j++) c[j] = lo[j] * s;
        }
        if (mlo + 1 < M) {
            float s = 1.f;
            if (SCALE) s = g_norm_out[(mlo + 1 < NN) ? mlo + 1 : mlo + 1 - NN];
            float* c = g_bufA + (mlo + 1) * HD + tx * 6;
#pragma unroll
            for (int j = 0; j < 6; j++) c[j] = hi[j] * s;
        }
    }
}

// ---------------- SpMM: one warp per (view,node) row ----------------
// Lanes 0..23 each own a float4 feature chunk: full 96-float accumulator lives
// across the warp, no smem, no block barrier.
// L1 (LAST=false): reads P (=g_bufA[0..N)), per-view perm gather + norm_out[s]
//   scale, writes activations to g_bufB.
// L2 (LAST=true): reads g_bufA (2N rows, pre-scaled) and fuses the readout:
//   out[row] = dot(PReLU(agg*norm_in + b), rowsum(Wm)) + sum(bm).
template <bool LAST>
__global__ __launch_bounds__(256)
void k_spmm(const int* __restrict__ perm,
            const float* __restrict__ bvec, const float* __restrict__ avec,
            float* __restrict__ out) {
    int w = (blockIdx.x * blockDim.x + threadIdx.x) >> 5;
    int lane = threadIdx.x & 31;
    if (w >= 2 * NN) return;
    int v = (w >= NN) ? 1 : 0;
    int i = w - v * NN;

    int beg = g_coff[i];
    int end = g_coff[i + 1];
    bool act = lane < 24;
    int c4 = lane * 4;

    float4 acc = make_float4(0.f, 0.f, 0.f, 0.f);
    for (int e = beg; e < end; e++) {
        int s = __ldg(&g_csr_src[e]);          // broadcast across warp
        const float* __restrict__ row;
        float sc;
        if (!LAST) {
            int rs = v ? __ldg(&perm[s]) : s;
            sc = g_norm_out[s];
            row = g_bufA + rs * HD;
        } else {
            sc = 1.f;
            row = g_bufA + (v * NN + s) * HD;
        }
        if (act) {
            float4 p = *(const float4*)(row + c4);
            acc.x += sc * p.x;
            acc.y += sc * p.y;
            acc.z += sc * p.z;
            acc.w += sc * p.w;
        }
    }

    float ni = g_norm_in[i];
    float partial = 0.f;
    if (act) {
        float4 bb = *(const float4*)(bvec + c4);
        float4 aa = *(const float4*)(avec + c4);
        float4 h;
        h.x = acc.x * ni + bb.x;
        h.y = acc.y * ni + bb.y;
        h.z = acc.z * ni + bb.z;
        h.w = acc.w * ni + bb.w;
        h.x = (h.x >= 0.f) ? h.x : aa.x * h.x;
        h.y = (h.y >= 0.f) ? h.y : aa.y * h.y;
        h.z = (h.z >= 0.f) ? h.z : aa.z * h.z;
        h.w = (h.w >= 0.f) ? h.w : aa.w * h.w;
        if (!LAST) {
            *(float4*)(g_bufB + (v * NN + i) * HD + c4) = h;
        } else {
            float4 wv = *(const float4*)(g_wv + c4);
            partial = h.x * wv.x + h.y * wv.y + h.z * wv.z + h.w * wv.w;
        }
    }
    if (LAST) {
#pragma unroll
        for (int o = 16; o; o >>= 1) partial += __shfl_down_sync(0xFFFFFFFFu, partial, o);
        if (lane == 0) out[v * NN + i] = partial + g_bmsum;
    }
}

// ---------------- launch ----------------
extern "C" void kernel_launch(void* const* d_in, const int* in_sizes, int n_in,
                              void* d_out, int out_size) {
    const float* x   = (const float*)d_in[0];
    const int*   src = (const int*)d_in[1];
    const int*   dst = (const int*)d_in[2];
    const int*   perm= (const int*)d_in[3];
    const float* W1  = (const float*)d_in[4];
    const float* b1  = (const float*)d_in[5];
    const float* a1  = (const float*)d_in[6];
    const float* W2  = (const float*)d_in[7];
    const float* b2  = (const float*)d_in[8];
    const float* a2  = (const float*)d_in[9];
    const float* Wm  = (const float*)d_in[10];
    const float* bm  = (const float*)d_in[11];
    float* out = (float*)d_out;

    // launches 0-2: degree prep
    k_zero<<<(NN + 255) / 256, 256>>>();
    k_deg<<<(NE + 255) / 256, 256>>>(src, dst);
    k_norm<<<(NN + 255) / 256, 256>>>();

    // launch 3: layer-1 GEMM (independent of CSR prep; placed here so ncu's
    // fixed capture slot lands on it)
    k_gemm<FIN, 20, false><<<(NN + 127) / 128, 256>>>(x, W1, NN);

    // CSR build + readout prep
    int nb = (NN + 1023) / 1024;
    k_scan_part<<<nb, 1024>>>();
    k_scan_top<<<1, 32>>>(nb);
    k_scan_add<<<nb, 1024>>>();
    k_scatter<<<(NE + 255) / 256, 256>>>(src, dst);
    k_wv<<<1, HD>>>(Wm, bm);

    // layer 1 SpMM (norm_out folded in, both views gather from P = x@W1)
    k_spmm<false><<<(2 * NN + 7) / 8, 256>>>(perm, b1, a1, nullptr);

    // layer 2: bufA = norm_out * (bufB @ W2), then SpMM fused with readout
    k_gemm<HD, 16, true><<<(2 * NN + 127) / 128, 256>>>(nullptr, W2, 2 * NN);
    k_spmm<true><<<(2 * NN + 7) / 8, 256>>>(perm, b2, a2, out);
}

// round 6
// speedup vs baseline: 1.5695x; 1.5695x over previous
#include <cuda_runtime.h>

#define NN 50000
#define NE 800000
#define FIN 500
#define HD 96

// ---------------- device scratch (no allocations allowed) ----------------
__device__ int   g_cnt_out[NN];
__device__ int   g_cnt_in[NN];
__device__ float g_norm_out[NN];
__device__ float g_norm_in[NN];
__device__ int   g_coff[NN + 1];
__device__ int   g_cursor[NN];
__device__ int   g_csr_src[NE];
__device__ int   g_bsums[64];
__device__ float g_bufA[2 * NN * HD];   // GEMM outputs
__device__ float g_bufB[2 * NN * HD];   // SpMM outputs (layer-1 activations)
__device__ float g_wv[HD];
__device__ float g_bmsum;

// ---------------- packed f32x2 helpers (sm_103a) ----------------
typedef unsigned long long u64;

__device__ __forceinline__ u64 pk2(float v) {
    u64 r;
    asm("mov.b64 %0, {%1, %1};" : "=l"(r) : "r"(__float_as_uint(v)));
    return r;
}
__device__ __forceinline__ u64 fma2(u64 a, u64 b, u64 c) {
    u64 d;
    asm("fma.rn.f32x2 %0, %1, %2, %3;" : "=l"(d) : "l"(a), "l"(b), "l"(c));
    return d;
}
__device__ __forceinline__ void upk(u64 v, float& lo, float& hi) {
    unsigned int l, h;
    asm("mov.b64 {%0, %1}, %2;" : "=r"(l), "=r"(h) : "l"(v));
    lo = __uint_as_float(l);
    hi = __uint_as_float(h);
}

// ---------------- degrees / norms ----------------
__global__ void k_zero() {
    int i = blockIdx.x * blockDim.x + threadIdx.x;
    if (i < NN) { g_cnt_out[i] = 0; g_cnt_in[i] = 0; }
}

__global__ void k_deg(const int* __restrict__ src, const int* __restrict__ dst) {
    int e = blockIdx.x * blockDim.x + threadIdx.x;
    if (e < NE) {
        atomicAdd(&g_cnt_out[src[e]], 1);
        atomicAdd(&g_cnt_in[dst[e]], 1);
    }
}

__global__ void k_norm() {
    int i = blockIdx.x * blockDim.x + threadIdx.x;
    if (i < NN) {
        g_norm_out[i] = rsqrtf((float)max(g_cnt_out[i], 1));
        g_norm_in[i]  = rsqrtf((float)max(g_cnt_in[i], 1));
    }
}

// ---------------- CSR build ----------------
__global__ void k_scan_part() {
    __shared__ int s[1024];
    int t = threadIdx.x;
    int i = blockIdx.x * 1024 + t;
    int c = (i < NN) ? g_cnt_in[i] : 0;
    s[t] = c;
    __syncthreads();
    for (int off = 1; off < 1024; off <<= 1) {
        int v = (t >= off) ? s[t - off] : 0;
        __syncthreads();
        s[t] += v;
        __syncthreads();
    }
    if (i < NN) g_coff[i] = s[t] - c;
    if (t == 1023) g_bsums[blockIdx.x] = s[t];
}

__global__ void k_scan_top(int nb) {
    if (threadIdx.x == 0) {
        int run = 0;
        for (int b = 0; b < nb; b++) { int v = g_bsums[b]; g_bsums[b] = run; run += v; }
    }
}

__global__ void k_scan_add() {
    int i = blockIdx.x * 1024 + threadIdx.x;
    if (i < NN) {
        int v = g_coff[i] + g_bsums[blockIdx.x];
        g_coff[i] = v;
        g_cursor[i] = v;
    }
    if (i == 0) g_coff[NN] = NE;
}

__global__ void k_scatter(const int* __restrict__ src, const int* __restrict__ dst) {
    int e = blockIdx.x * blockDim.x + threadIdx.x;
    if (e < NE) {
        int d = dst[e];
        int p = atomicAdd(&g_cursor[d], 1);
        g_csr_src[p] = src[e];
    }
}

// ---------------- Wm row-sums + bm sum ----------------
__global__ void k_wv(const float* __restrict__ Wm, const float* __restrict__ bm) {
    int t = threadIdx.x;
    if (t < HD) {
        float s = 0.f;
        for (int j = 0; j < HD; j++) s += Wm[t * HD + j];
        g_wv[t] = s;
        if (t == 0) {
            float bs = 0.f;
            for (int j = 0; j < HD; j++) bs += bm[j];
            g_bmsum = bs;
        }
    }
}

// ---------------- double-buffered fp32 GEMM with packed f32x2 FMA ----------
// C(g_bufA) = A @ W  [* norm_out in epilogue if SCALE]
// BM=128, BN=96, 256 threads; per thread 8 rows x 6 cols as 4 row-pairs x 6.
// Two smem buffers; chunk c+1 is prefetched into registers while computing
// chunk c, then stored to the idle buffer. One barrier per chunk.
// NOTE: A-tile float4 count (AV) is NOT always a multiple of 256 (BK=20 ->
// AV=640); the prefetch loops use ceil + predicate.
template <int K, int BK, bool SCALE>
__global__ __launch_bounds__(256, 2)
void k_gemm(const float* __restrict__ Ain, const float* __restrict__ W, int M) {
    static_assert(BK % 4 == 0 && K % BK == 0, "");
    constexpr int NC  = K / BK;              // chunks
    constexpr int AV  = 128 * BK / 4;        // float4 loads per A tile
    constexpr int NA  = (AV + 255) / 256;    // per-thread A float4 count (ceil)
    constexpr int BEL = BK * HD;             // B tile elements
    constexpr int NB  = (BEL + 255) / 256;   // per-thread B scalar count (ceil)

    __shared__ float As[2][BK][132];         // [buf][k][row]
    __shared__ float Bs[2][BK][HD];

    const float* __restrict__ A = SCALE ? (const float*)g_bufB : Ain;
    const int tid = threadIdx.x;
    const int tx = tid & 15;
    const int ty = tid >> 4;
    const int m0 = blockIdx.x * 128;

    float4 ra[NA];
    float  rb[NB];

    auto loadA = [&](int k0) {
#pragma unroll
        for (int l = 0; l < NA; l++) {
            int j = tid + l * 256;
            if (j < AV) {
                int r = j / (BK / 4);
                int q = j % (BK / 4);
                int m = m0 + r;
                ra[l] = (m < M) ? *(const float4*)&A[(long)m * K + k0 + q * 4]
                                : make_float4(0.f, 0.f, 0.f, 0.f);
            }
        }
    };
    auto loadB = [&](int k0) {
#pragma unroll
        for (int l = 0; l < NB; l++) {
            int j = tid + l * 256;
            if (j < BEL) {
                int k = j / HD;
                int n = j - k * HD;
                rb[l] = W[(long)(k0 + k) * HD + n];
            }
        }
    };
    auto store = [&](int buf) {
#pragma unroll
        for (int l = 0; l < NA; l++) {
            int j = tid + l * 256;
            if (j < AV) {
                int r = j / (BK / 4);
                int q = j % (BK / 4);
                As[buf][q * 4 + 0][r] = ra[l].x;
                As[buf][q * 4 + 1][r] = ra[l].y;
                As[buf][q * 4 + 2][r] = ra[l].z;
                As[buf][q * 4 + 3][r] = ra[l].w;
            }
        }
#pragma unroll
        for (int l = 0; l < NB; l++) {
            int j = tid + l * 256;
            if (j < BEL) {
                int k = j / HD;
                int n = j - k * HD;
                Bs[buf][k][n] = rb[l];
            }
        }
    };

    u64 accp[4][6];
#pragma unroll
    for (int i = 0; i < 4; i++)
#pragma unroll
        for (int j = 0; j < 6; j++) accp[i][j] = 0ull;

    loadA(0);
    loadB(0);
    store(0);
    __syncthreads();

    int buf = 0;
    for (int c = 0; c < NC; c++) {
        if (c + 1 < NC) {                     // issue next-chunk LDGs early
            loadA((c + 1) * BK);
            loadB((c + 1) * BK);
        }
#pragma unroll
        for (int k = 0; k < BK; k++) {
            const u64* ap = (const u64*)&As[buf][k][ty * 8];
            u64 a01 = ap[0], a23 = ap[1], a45 = ap[2], a67 = ap[3];
            float2 q0 = *(const float2*)&Bs[buf][k][tx * 6];
            float2 q1 = *(const float2*)&Bs[buf][k][tx * 6 + 2];
            float2 q2 = *(const float2*)&Bs[buf][k][tx * 6 + 4];
            float b[6] = {q0.x, q0.y, q1.x, q1.y, q2.x, q2.y};
#pragma unroll
            for (int j = 0; j < 6; j++) {
                u64 bb = pk2(b[j]);
                accp[0][j] = fma2(a01, bb, accp[0][j]);
                accp[1][j] = fma2(a23, bb, accp[1][j]);
                accp[2][j] = fma2(a45, bb, accp[2][j]);
                accp[3][j] = fma2(a67, bb, accp[3][j]);
            }
        }
        if (c + 1 < NC) {
            store(buf ^ 1);                   // idle buffer
            __syncthreads();                  // publish before anyone reads it
            buf ^= 1;
        }
    }

#pragma unroll
    for (int i = 0; i < 4; i++) {
        int mlo = m0 + ty * 8 + 2 * i;
        float lo[6], hi[6];
#pragma unroll
        for (int j = 0; j < 6; j++) upk(accp[i][j], lo[j], hi[j]);
        if (mlo < M) {
            float s = 1.f;
            if (SCALE) s = g_norm_out[(mlo < NN) ? mlo : mlo - NN];
            float* c = g_bufA + (long)mlo * HD + tx * 6;
#pragma unroll
            for (int j = 0; j < 6; j++) c[j] = lo[j] * s;
        }
        if (mlo + 1 < M) {
            float s = 1.f;
            if (SCALE) s = g_norm_out[(mlo + 1 < NN) ? mlo + 1 : mlo + 1 - NN];
            float* c = g_bufA + (long)(mlo + 1) * HD + tx * 6;
#pragma unroll
            for (int j = 0; j < 6; j++) c[j] = hi[j] * s;
        }
    }
}

// ---------------- SpMM block-per-(view,node): 24 chunks x 4 edge slots ------
// L1 (LAST=false): reads P (=g_bufA[0..N)), per-view perm gather + norm_out[s]
//   scale, writes activations to g_bufB.
// L2 (LAST=true): reads g_bufA (2N rows, pre-scaled) and fuses the readout:
//   out[row] = dot(PReLU(agg*norm_in + b), rowsum(Wm)) + sum(bm).
template <bool LAST>
__global__ __launch_bounds__(96)
void k_spmm(const int* __restrict__ perm,
            const float* __restrict__ bvec, const float* __restrict__ avec,
            float* __restrict__ out) {
    int b = blockIdx.x;
    int v = (b >= NN) ? 1 : 0;
    int i = b - v * NN;
    int t = threadIdx.x;
    int c = t % 24;
    int slot = t / 24;

    int beg = g_coff[i];
    int end = g_coff[i + 1];

    float4 acc = make_float4(0.f, 0.f, 0.f, 0.f);
    for (int e = beg + slot; e < end; e += 4) {
        int s = g_csr_src[e];
        const float* row;
        float sc = 1.f;
        if (!LAST) {
            int rs = v ? perm[s] : s;
            sc = g_norm_out[s];
            row = g_bufA + (long)rs * HD;
        } else {
            row = g_bufA + (long)(v * NN + s) * HD;
        }
        float4 p = *(const float4*)(row + c * 4);
        if (!LAST) {
            acc.x += sc * p.x; acc.y += sc * p.y; acc.z += sc * p.z; acc.w += sc * p.w;
        } else {
            acc.x += p.x; acc.y += p.y; acc.z += p.z; acc.w += p.w;
        }
    }

    __shared__ float4 red[96];
    __shared__ float sred[24];
    red[t] = acc;
    __syncthreads();
    if (slot == 0) {
        float4 r = red[c];
        float4 r1 = red[c + 24];
        float4 r2 = red[c + 48];
        float4 r3 = red[c + 72];
        r.x += r1.x + r2.x + r3.x;
        r.y += r1.y + r2.y + r3.y;
        r.z += r1.z + r2.z + r3.z;
        r.w += r1.w + r2.w + r3.w;

        float ni = g_norm_in[i];
        float4 bb = *(const float4*)(bvec + c * 4);
        float4 aa = *(const float4*)(avec + c * 4);
        float4 h;
        h.x = r.x * ni + bb.x;
        h.y = r.y * ni + bb.y;
        h.z = r.z * ni + bb.z;
        h.w = r.w * ni + bb.w;
        h.x = (h.x >= 0.f) ? h.x : aa.x * h.x;
        h.y = (h.y >= 0.f) ? h.y : aa.y * h.y;
        h.z = (h.z >= 0.f) ? h.z : aa.z * h.z;
        h.w = (h.w >= 0.f) ? h.w : aa.w * h.w;
        if (!LAST) {
            *(float4*)(g_bufB + (long)(v * NN + i) * HD + c * 4) = h;
        } else {
            float4 wv = *(const float4*)(g_wv + c * 4);
            sred[c] = h.x * wv.x + h.y * wv.y + h.z * wv.z + h.w * wv.w;
        }
    }
    if (LAST) {
        __syncthreads();
        if (t == 0) {
            float s = 0.f;
#pragma unroll
            for (int j = 0; j < 24; j++) s += sred[j];
            out[v * NN + i] = s + g_bmsum;
        }
    }
}

// ---------------- launch ----------------
extern "C" void kernel_launch(void* const* d_in, const int* in_sizes, int n_in,
                              void* d_out, int out_size) {
    const float* x   = (const float*)d_in[0];
    const int*   src = (const int*)d_in[1];
    const int*   dst = (const int*)d_in[2];
    const int*   perm= (const int*)d_in[3];
    const float* W1  = (const float*)d_in[4];
    const float* b1  = (const float*)d_in[5];
    const float* a1  = (const float*)d_in[6];
    const float* W2  = (const float*)d_in[7];
    const float* b2  = (const float*)d_in[8];
    const float* a2  = (const float*)d_in[9];
    const float* Wm  = (const float*)d_in[10];
    const float* bm  = (const float*)d_in[11];
    float* out = (float*)d_out;

    // launches 0-2: degree prep
    k_zero<<<(NN + 255) / 256, 256>>>();
    k_deg<<<(NE + 255) / 256, 256>>>(src, dst);
    k_norm<<<(NN + 255) / 256, 256>>>();

    // launch 3: layer-1 GEMM (ncu capture slot)
    k_gemm<FIN, 20, false><<<(NN + 127) / 128, 256>>>(x, W1, NN);

    // CSR build + readout prep
    int nb = (NN + 1023) / 1024;
    k_scan_part<<<nb, 1024>>>();
    k_scan_top<<<1, 32>>>(nb);
    k_scan_add<<<nb, 1024>>>();
    k_scatter<<<(NE + 255) / 256, 256>>>(src, dst);
    k_wv<<<1, HD>>>(Wm, bm);

    // layer 1 SpMM (norm_out folded in, both views gather from P = x@W1)
    k_spmm<false><<<2 * NN, 96>>>(perm, b1, a1, nullptr);

    // layer 2: bufA = norm_out * (bufB @ W2), then SpMM fused with readout
    k_gemm<HD, 16, true><<<(2 * NN + 127) / 128, 256>>>(nullptr, W2, 2 * NN);
    k_spmm<true><<<2 * NN, 96>>>(perm, b2, a2, out);
}